// round 1
// baseline (speedup 1.0000x reference)
#include <cuda_runtime.h>

#define FFT_N 4096
#define LOGN  12
#define NB    16
#define ND    128
#define NLANES (NB*ND)   // 2048 lanes
#define TOPK  8
#define NT    256

// -------- scratch (device globals: allocation-free) --------
__device__ float  g_Qt[(size_t)NLANES * FFT_N];
__device__ float  g_Kt[(size_t)NLANES * FFT_N];
__device__ float  g_Vt[(size_t)NLANES * FFT_N];
__device__ float  g_Ot[(size_t)NLANES * FFT_N];
__device__ float2 g_tw[FFT_N / 2];

// -------- twiddle table: g_tw[k] = exp(-2*pi*i*k/N) --------
__global__ void twiddle_init_kernel() {
    int i = blockIdx.x * blockDim.x + threadIdx.x;
    if (i < FFT_N / 2) {
        float s, c;
        sincospif(-2.0f * (float)i / (float)FFT_N, &s, &c);
        g_tw[i] = make_float2(c, s);
    }
}

// -------- tiled transpose: dst[b, c, r] = src[b, r, c];  src is [B, R, C]; R,C % 32 == 0
__global__ void transpose_kernel(float* __restrict__ dst, const float* __restrict__ src,
                                 int R, int C) {
    __shared__ float tile[32][33];
    int b = blockIdx.z;
    const float* s = src + (size_t)b * R * C;
    float*       d = dst + (size_t)b * R * C;
    int c0 = blockIdx.x * 32, r0 = blockIdx.y * 32;
#pragma unroll
    for (int i = threadIdx.y; i < 32; i += 8)
        tile[i][threadIdx.x] = s[(size_t)(r0 + i) * C + (c0 + threadIdx.x)];
    __syncthreads();
#pragma unroll
    for (int i = threadIdx.y; i < 32; i += 8)
        d[(size_t)(c0 + i) * R + (r0 + threadIdx.x)] = tile[threadIdx.x][i];
}

// -------- main per-lane kernel --------
__global__ __launch_bounds__(NT)
void autocorr_lane_kernel(const float* __restrict__ Qt, const float* __restrict__ Kt,
                          const float* __restrict__ Vt, float* __restrict__ Ot) {
    extern __shared__ char smraw[];
    float2* Z    = (float2*)smraw;                        // 4096 float2 = 32 KB
    float2* tw   = (float2*)(smraw + FFT_N * 8);          // 2048 float2 = 16 KB
    float*  Vs   = (float*)tw;                            // reuse after FFTs (16 KB)
    float*  corr = (float*)Z;                             // reuse first 16 KB of Z
    float*  s_w   = (float*)(smraw + 49152);
    int*    s_tau = (int*)  (smraw + 49152 + TOPK * 4);
    float*  s_rv  = (float*)(smraw + 49152 + TOPK * 8);
    int*    s_ri  = (int*)  (smraw + 49152 + TOPK * 8 + 32);

    const int tid  = threadIdx.x;
    const int lane = blockIdx.x;
    const float4* q4 = (const float4*)(Qt + (size_t)lane * FFT_N);
    const float4* k4 = (const float4*)(Kt + (size_t)lane * FFT_N);
    const float4* v4 = (const float4*)(Vt + (size_t)lane * FFT_N);
    float* outp = Ot + (size_t)lane * FFT_N;

    // load z = Q + i*K (coalesced float4), and twiddles to smem
#pragma unroll
    for (int r = 0; r < 4; r++) {
        int i4 = tid + NT * r;
        float4 qq = q4[i4];
        float4 kk = k4[i4];
        int b = i4 * 4;
        Z[b + 0] = make_float2(qq.x, kk.x);
        Z[b + 1] = make_float2(qq.y, kk.y);
        Z[b + 2] = make_float2(qq.z, kk.z);
        Z[b + 3] = make_float2(qq.w, kk.w);
    }
#pragma unroll
    for (int r = 0; r < 8; r++) tw[tid + NT * r] = g_tw[tid + NT * r];
    __syncthreads();

    // forward radix-2 DIF: natural -> bit-reversed
    for (int s = LOGN; s >= 1; s--) {
        const int half = 1 << (s - 1);
        const int ts   = FFT_N >> s;
#pragma unroll
        for (int r = 0; r < FFT_N / 2 / NT; r++) {
            int j  = tid + NT * r;
            int k  = j & (half - 1);
            int i0 = ((j >> (s - 1)) << s) | k;
            int i1 = i0 + half;
            float2 a = Z[i0], b = Z[i1];
            Z[i0] = make_float2(a.x + b.x, a.y + b.y);
            float dx = a.x - b.x, dy = a.y - b.y;
            float2 w = tw[k * ts];
            Z[i1] = make_float2(dx * w.x - dy * w.y, dx * w.y + dy * w.x);
        }
        __syncthreads();
    }

    // spectral unpack + multiply in bit-reversed domain:
    // Qhat = (Z[f] + conj(Z[N-f]))/2 ; Khat = (Z[f] - conj(Z[N-f]))/(2i)
    // C[f] = Qhat * conj(Khat); C[N-f] = conj(C[f]).
    // Position of freq f is brev(f). Pairs partition positions -> in-place safe.
    for (int f = tid; f <= FFT_N / 2; f += NT) {
        int p  = (int)(__brev((unsigned)f) >> (32 - LOGN));
        int p2 = (int)(__brev((unsigned)((FFT_N - f) & (FFT_N - 1))) >> (32 - LOGN));
        float2 A  = Z[p];
        float2 Bv = Z[p2];
        float qr = 0.5f * (A.x + Bv.x);
        float qi = 0.5f * (A.y - Bv.y);
        float kr = 0.5f * (A.y + Bv.y);
        float ki = 0.5f * (Bv.x - A.x);
        float cr = qr * kr + qi * ki;   // (qr,qi) * (kr,-ki)
        float ci = qi * kr - qr * ki;
        Z[p]  = make_float2(cr, ci);
        Z[p2] = make_float2(cr, -ci);
    }
    __syncthreads();

    // inverse radix-2 DIT (conjugate twiddles): bit-reversed -> natural
    for (int s = 1; s <= LOGN; s++) {
        const int half = 1 << (s - 1);
        const int ts   = FFT_N >> s;
#pragma unroll
        for (int r = 0; r < FFT_N / 2 / NT; r++) {
            int j  = tid + NT * r;
            int k  = j & (half - 1);
            int i0 = ((j >> (s - 1)) << s) | k;
            int i1 = i0 + half;
            float2 w = tw[k * ts];
            float2 a = Z[i0], b = Z[i1];
            float tr = b.x * w.x + b.y * w.y;   // b * conj(w)
            float ti = b.y * w.x - b.x * w.y;
            Z[i0] = make_float2(a.x + tr, a.y + ti);
            Z[i1] = make_float2(a.x - tr, a.y - ti);
        }
        __syncthreads();
    }

    // extract corr = Re(Z)/N  (two-phase: regs first, then overlay-write)
    float myv[16];
#pragma unroll
    for (int r = 0; r < 16; r++) myv[r] = Z[tid + NT * r].x * (1.0f / FFT_N);
    __syncthreads();
#pragma unroll
    for (int r = 0; r < 16; r++) corr[tid + NT * r] = myv[r];
    // load V into smem (overlays twiddle region — no longer needed)
#pragma unroll
    for (int r = 0; r < 4; r++) {
        int i4 = tid + NT * r;
        ((float4*)Vs)[i4] = v4[i4];
    }
    __syncthreads();

    // top-8 (sequential argmax passes; deterministic low-index tie-break)
    const int wid = tid >> 5, lid = tid & 31;
    for (int sel = 0; sel < TOPK; sel++) {
        float best = -3.4e38f;
        int   bidx = 0;
#pragma unroll
        for (int r = 0; r < 16; r++) {
            int i = tid + NT * r;
            float v = corr[i];
            if (v > best) { best = v; bidx = i; }
        }
#pragma unroll
        for (int off = 16; off > 0; off >>= 1) {
            float ov = __shfl_down_sync(0xffffffffu, best, off);
            int   oi = __shfl_down_sync(0xffffffffu, bidx, off);
            if (ov > best || (ov == best && oi < bidx)) { best = ov; bidx = oi; }
        }
        if (lid == 0) { s_rv[wid] = best; s_ri[wid] = bidx; }
        __syncthreads();
        if (tid == 0) {
            float bb = s_rv[0]; int bi = s_ri[0];
#pragma unroll
            for (int w2 = 1; w2 < NT / 32; w2++) {
                if (s_rv[w2] > bb || (s_rv[w2] == bb && s_ri[w2] < bi)) {
                    bb = s_rv[w2]; bi = s_ri[w2];
                }
            }
            s_w[sel]   = bb;
            s_tau[sel] = bi;
            corr[bi]   = -3.4e38f;
        }
        __syncthreads();
    }

    // time-delay aggregation: out[t] = sum_k w_k * V[(t + tau_k) mod N]
    float wv[TOPK]; int tv[TOPK];
#pragma unroll
    for (int kk = 0; kk < TOPK; kk++) { wv[kk] = s_w[kk]; tv[kk] = s_tau[kk]; }
#pragma unroll 2
    for (int r = 0; r < 16; r++) {
        int t = tid + NT * r;
        float acc = 0.0f;
#pragma unroll
        for (int kk = 0; kk < TOPK; kk++)
            acc += wv[kk] * Vs[(t + tv[kk]) & (FFT_N - 1)];
        outp[t] = acc;
    }
}

// -------- launch --------
extern "C" void kernel_launch(void* const* d_in, const int* in_sizes, int n_in,
                              void* d_out, int out_size) {
    (void)in_sizes; (void)n_in; (void)out_size;
    const float* Q = (const float*)d_in[0];
    const float* K = (const float*)d_in[1];
    const float* V = (const float*)d_in[2];
    float* out = (float*)d_out;

    float *Qt, *Kt, *Vt, *Ot;
    cudaGetSymbolAddress((void**)&Qt, g_Qt);
    cudaGetSymbolAddress((void**)&Kt, g_Kt);
    cudaGetSymbolAddress((void**)&Vt, g_Vt);
    cudaGetSymbolAddress((void**)&Ot, g_Ot);

    twiddle_init_kernel<<<(FFT_N / 2 + 255) / 256, 256>>>();

    dim3 tb(32, 8);
    // [B, S, D] -> [B, D, S]
    transpose_kernel<<<dim3(ND / 32, FFT_N / 32, NB), tb>>>(Qt, Q, FFT_N, ND);
    transpose_kernel<<<dim3(ND / 32, FFT_N / 32, NB), tb>>>(Kt, K, FFT_N, ND);
    transpose_kernel<<<dim3(ND / 32, FFT_N / 32, NB), tb>>>(Vt, V, FFT_N, ND);

    size_t sh = 49152 + 128;
    cudaFuncSetAttribute(autocorr_lane_kernel,
                         cudaFuncAttributeMaxDynamicSharedMemorySize, (int)sh);
    autocorr_lane_kernel<<<NLANES, NT, sh>>>(Qt, Kt, Vt, Ot);

    // [B, D, S] -> [B, S, D]
    transpose_kernel<<<dim3(FFT_N / 32, ND / 32, NB), tb>>>(out, Ot, ND, FFT_N);
}

// round 2
// speedup vs baseline: 2.1325x; 2.1325x over previous
#include <cuda_runtime.h>
#include <float.h>

#define FFT_N 4096
#define LOGN  12
#define NB    16
#define ND    128
#define NLANES (NB*ND)   // 2048 lanes
#define TOPK  8
#define NT    256

// XOR swizzle: conflict-free for all three ownership patterns
#define SWZ(i) ((i) ^ ((((unsigned)(i)) >> 4) & 15u))

// -------- scratch (device globals: allocation-free) --------
__device__ float  g_Qt[(size_t)NLANES * FFT_N];
__device__ float  g_Kt[(size_t)NLANES * FFT_N];
__device__ float  g_Vt[(size_t)NLANES * FFT_N];
__device__ float  g_Ot[(size_t)NLANES * FFT_N];
__device__ float2 g_tw[FFT_N];   // g_tw[m] = exp(-2*pi*i*m/N), m in [0, 4096)

// -------- complex helpers --------
__device__ __forceinline__ float2 cadd(float2 a, float2 b) { return make_float2(a.x + b.x, a.y + b.y); }
__device__ __forceinline__ float2 csub(float2 a, float2 b) { return make_float2(a.x - b.x, a.y - b.y); }
__device__ __forceinline__ float2 cmul(float2 a, float2 b) {
    return make_float2(fmaf(a.x, b.x, -a.y * b.y), fmaf(a.x, b.y, a.y * b.x));
}
// a * conj(b)
__device__ __forceinline__ float2 cmulc(float2 a, float2 b) {
    return make_float2(fmaf(a.x, b.x, a.y * b.y), fmaf(a.y, b.x, -a.x * b.y));
}

// forward radix-4 DIF butterfly (legs a,b,c,d at strides 0,Q,2Q,3Q), then twiddle
__device__ __forceinline__ void fwd4(float2& a, float2& b, float2& c, float2& d,
                                     float2 w1, float2 w2, float2 w3) {
    float2 t0 = cadd(a, c), t1 = csub(a, c);
    float2 t2 = cadd(b, d), bd = csub(b, d);
    float2 t3 = make_float2(bd.y, -bd.x);        // -i * (b - d)
    a = cadd(t0, t2);
    b = cmul(cadd(t1, t3), w1);
    c = cmul(csub(t0, t2), w2);
    d = cmul(csub(t1, t3), w3);
}
__device__ __forceinline__ void fwd4_nw(float2& a, float2& b, float2& c, float2& d) {
    float2 t0 = cadd(a, c), t1 = csub(a, c);
    float2 t2 = cadd(b, d), bd = csub(b, d);
    float2 t3 = make_float2(bd.y, -bd.x);
    a = cadd(t0, t2); b = cadd(t1, t3); c = csub(t0, t2); d = csub(t1, t3);
}
// inverse radix-4 DIT butterfly: conj-twiddle inputs, then IDFT4 (no 1/4 scale)
__device__ __forceinline__ void inv4(float2& a, float2& b, float2& c, float2& d,
                                     float2 w1, float2 w2, float2 w3) {
    float2 u1 = cmulc(b, w1), u2 = cmulc(c, w2), u3 = cmulc(d, w3);
    float2 s0 = cadd(a, u2), d0 = csub(a, u2);
    float2 s1 = cadd(u1, u3), d1 = csub(u1, u3);
    float2 id1 = make_float2(-d1.y, d1.x);       // +i * (u1 - u3)
    a = cadd(s0, s1); b = cadd(d0, id1); c = csub(s0, s1); d = csub(d0, id1);
}
__device__ __forceinline__ void inv4_nw(float2& a, float2& b, float2& c, float2& d) {
    float2 s0 = cadd(a, c), d0 = csub(a, c);
    float2 s1 = cadd(b, d), d1 = csub(b, d);
    float2 id1 = make_float2(-d1.y, d1.x);
    a = cadd(s0, s1); b = cadd(d0, id1); c = csub(s0, s1); d = csub(d0, id1);
}

// -------- twiddle table init --------
__global__ void twiddle_init_kernel() {
    int i = blockIdx.x * blockDim.x + threadIdx.x;
    if (i < FFT_N) {
        float s, c;
        sincospif(-2.0f * (float)i / (float)FFT_N, &s, &c);
        g_tw[i] = make_float2(c, s);
    }
}

// -------- input transposes (Q,K,V fused): [B,S,D] -> [B,D,S] --------
__global__ void transpose_in_kernel(const float* __restrict__ Q,
                                    const float* __restrict__ K,
                                    const float* __restrict__ V) {
    __shared__ float tile[32][33];
    int z = blockIdx.z, b = z & 15, sel = z >> 4;
    const float* s = (sel == 0 ? Q : sel == 1 ? K : V) + (size_t)b * FFT_N * ND;
    float*       d = (sel == 0 ? g_Qt : sel == 1 ? g_Kt : g_Vt) + (size_t)b * FFT_N * ND;
    int c0 = blockIdx.x * 32, r0 = blockIdx.y * 32;   // over C=ND, R=FFT_N
#pragma unroll
    for (int i = threadIdx.y; i < 32; i += 8)
        tile[i][threadIdx.x] = s[(size_t)(r0 + i) * ND + (c0 + threadIdx.x)];
    __syncthreads();
#pragma unroll
    for (int i = threadIdx.y; i < 32; i += 8)
        d[(size_t)(c0 + i) * FFT_N + (r0 + threadIdx.x)] = tile[threadIdx.x][i];
}

// -------- output transpose: [B,D,S] -> [B,S,D] --------
__global__ void transpose_out_kernel(float* __restrict__ dst) {
    __shared__ float tile[32][33];
    int b = blockIdx.z;
    const float* s = g_Ot + (size_t)b * ND * FFT_N;   // R=ND, C=FFT_N
    float*       d = dst  + (size_t)b * ND * FFT_N;
    int c0 = blockIdx.x * 32, r0 = blockIdx.y * 32;
#pragma unroll
    for (int i = threadIdx.y; i < 32; i += 8)
        tile[i][threadIdx.x] = s[(size_t)(r0 + i) * FFT_N + (c0 + threadIdx.x)];
    __syncthreads();
#pragma unroll
    for (int i = threadIdx.y; i < 32; i += 8)
        d[(size_t)(c0 + i) * ND + (r0 + threadIdx.x)] = tile[threadIdx.x][i];
}

// -------- main per-lane kernel: radix-4 register FFT --------
__global__ __launch_bounds__(NT, 3)
void autocorr_fft4_kernel(const float* __restrict__ Qt, const float* __restrict__ Kt,
                          const float* __restrict__ Vt, float* __restrict__ Ot) {
    extern __shared__ float2 Z[];                 // 4096 float2 = 32 KB, swizzled
    __shared__ float s_rv[NT / 32];
    __shared__ int   s_ri[NT / 32];
    __shared__ float s_w[TOPK];
    __shared__ int   s_tau[TOPK];

    const int t  = threadIdx.x;
    const int tm = t & 15;
    const int th = t >> 4;
    const size_t lane = blockIdx.x;
    const float* qp = Qt + lane * FFT_N;
    const float* kp = Kt + lane * FFT_N;

    float2 r[16];
#pragma unroll
    for (int j = 0; j < 16; j++)
        r[j] = make_float2(qp[t + 256 * j], kp[t + 256 * j]);

    // ===== forward pass 0 (ownership A: idx = t + 256j): Q=1024 then Q=256
#pragma unroll
    for (int c = 0; c < 4; c++) {
        float2 w1 = g_tw[t + 256 * c];
        float2 w2 = cmul(w1, w1), w3 = cmul(w2, w1);
        fwd4(r[c], r[c + 4], r[c + 8], r[c + 12], w1, w2, w3);
    }
    {
        float2 w1 = g_tw[4 * t];
        float2 w2 = cmul(w1, w1), w3 = cmul(w2, w1);
#pragma unroll
        for (int g = 0; g < 4; g++)
            fwd4(r[4 * g], r[4 * g + 1], r[4 * g + 2], r[4 * g + 3], w1, w2, w3);
    }
#pragma unroll
    for (int j = 0; j < 16; j++) Z[SWZ(t + 256 * j)] = r[j];
    __syncthreads();
#pragma unroll
    for (int j = 0; j < 16; j++) r[j] = Z[SWZ(256 * th + tm + 16 * j)];

    // ===== forward pass 1 (ownership B: idx = 256*th + tm + 16j): Q=64 then Q=16
#pragma unroll
    for (int c = 0; c < 4; c++) {
        float2 w1 = g_tw[16 * tm + 256 * c];
        float2 w2 = cmul(w1, w1), w3 = cmul(w2, w1);
        fwd4(r[c], r[c + 4], r[c + 8], r[c + 12], w1, w2, w3);
    }
    {
        float2 w1 = g_tw[64 * tm];
        float2 w2 = cmul(w1, w1), w3 = cmul(w2, w1);
#pragma unroll
        for (int g = 0; g < 4; g++)
            fwd4(r[4 * g], r[4 * g + 1], r[4 * g + 2], r[4 * g + 3], w1, w2, w3);
    }
#pragma unroll
    for (int j = 0; j < 16; j++) Z[SWZ(256 * th + tm + 16 * j)] = r[j];
    __syncthreads();
#pragma unroll
    for (int j = 0; j < 16; j++) r[j] = Z[SWZ(16 * t + j)];

    // ===== forward pass 2 (ownership C: idx = 16t + j): Q=4 then Q=1
#pragma unroll
    for (int c = 0; c < 4; c++) {
        float2 w1 = g_tw[256 * c];
        float2 w2 = cmul(w1, w1), w3 = cmul(w2, w1);
        fwd4(r[c], r[c + 4], r[c + 8], r[c + 12], w1, w2, w3);
    }
#pragma unroll
    for (int g = 0; g < 4; g++)
        fwd4_nw(r[4 * g], r[4 * g + 1], r[4 * g + 2], r[4 * g + 3]);
#pragma unroll
    for (int j = 0; j < 16; j++) Z[SWZ(16 * t + j)] = r[j];
    __syncthreads();

    // ===== spectral unpack + multiply in base-4 digit-reversed domain
    // Qhat = (Z[f]+conj(Z[N-f]))/2 ; Khat = (Z[f]-conj(Z[N-f]))/(2i); C = Qhat*conj(Khat)
    for (int f = t; f <= FFT_N / 2; f += NT) {
        int rb  = (int)(__brev((unsigned)f) >> 20);
        int p   = ((rb & 0x555) << 1) | ((rb >> 1) & 0x555);
        int f2  = (FFT_N - f) & (FFT_N - 1);
        int rb2 = (int)(__brev((unsigned)f2) >> 20);
        int p2  = ((rb2 & 0x555) << 1) | ((rb2 >> 1) & 0x555);
        float2 A  = Z[SWZ(p)];
        float2 Bv = Z[SWZ(p2)];
        float qr = 0.5f * (A.x + Bv.x);
        float qi = 0.5f * (A.y - Bv.y);
        float kr = 0.5f * (A.y + Bv.y);
        float ki = 0.5f * (Bv.x - A.x);
        float cr = qr * kr + qi * ki;
        float ci = qi * kr - qr * ki;
        Z[SWZ(p)]  = make_float2(cr, ci);
        Z[SWZ(p2)] = make_float2(cr, -ci);
    }
    __syncthreads();

    // ===== inverse pass 0 (ownership C): Q=1 (no tw) then Q=4
#pragma unroll
    for (int j = 0; j < 16; j++) r[j] = Z[SWZ(16 * t + j)];
#pragma unroll
    for (int g = 0; g < 4; g++)
        inv4_nw(r[4 * g], r[4 * g + 1], r[4 * g + 2], r[4 * g + 3]);
#pragma unroll
    for (int c = 0; c < 4; c++) {
        float2 w1 = g_tw[256 * c];
        float2 w2 = cmul(w1, w1), w3 = cmul(w2, w1);
        inv4(r[c], r[c + 4], r[c + 8], r[c + 12], w1, w2, w3);
    }
#pragma unroll
    for (int j = 0; j < 16; j++) Z[SWZ(16 * t + j)] = r[j];
    __syncthreads();
#pragma unroll
    for (int j = 0; j < 16; j++) r[j] = Z[SWZ(256 * th + tm + 16 * j)];

    // ===== inverse pass 1 (ownership B): Q=16 then Q=64
    {
        float2 w1 = g_tw[64 * tm];
        float2 w2 = cmul(w1, w1), w3 = cmul(w2, w1);
#pragma unroll
        for (int g = 0; g < 4; g++)
            inv4(r[4 * g], r[4 * g + 1], r[4 * g + 2], r[4 * g + 3], w1, w2, w3);
    }
#pragma unroll
    for (int c = 0; c < 4; c++) {
        float2 w1 = g_tw[16 * tm + 256 * c];
        float2 w2 = cmul(w1, w1), w3 = cmul(w2, w1);
        inv4(r[c], r[c + 4], r[c + 8], r[c + 12], w1, w2, w3);
    }
#pragma unroll
    for (int j = 0; j < 16; j++) Z[SWZ(256 * th + tm + 16 * j)] = r[j];
    __syncthreads();
#pragma unroll
    for (int j = 0; j < 16; j++) r[j] = Z[SWZ(t + 256 * j)];

    // ===== inverse pass 2 (ownership A): Q=256 then Q=1024
    {
        float2 w1 = g_tw[4 * t];
        float2 w2 = cmul(w1, w1), w3 = cmul(w2, w1);
#pragma unroll
        for (int g = 0; g < 4; g++)
            inv4(r[4 * g], r[4 * g + 1], r[4 * g + 2], r[4 * g + 3], w1, w2, w3);
    }
#pragma unroll
    for (int c = 0; c < 4; c++) {
        float2 w1 = g_tw[t + 256 * c];
        float2 w2 = cmul(w1, w1), w3 = cmul(w2, w1);
        inv4(r[c], r[c + 4], r[c + 8], r[c + 12], w1, w2, w3);
    }

    // corr (natural order) lives in regs: corr[t + 256j] = r[j].x / N
    float myv[16];
#pragma unroll
    for (int j = 0; j < 16; j++) myv[j] = r[j].x * (1.0f / (float)FFT_N);
    __syncthreads();   // all Z reads done before overlaying V

    // V into smem (overlays Z)
    float* Vs = (float*)Z;
    const float4* v4 = (const float4*)(Vt + lane * FFT_N);
#pragma unroll
    for (int rr = 0; rr < 4; rr++)
        ((float4*)Vs)[t + 256 * rr] = v4[t + 256 * rr];

    // ===== top-8 straight from registers
    const int wid = t >> 5, lid = t & 31;
    for (int sel = 0; sel < TOPK; sel++) {
        float best = -FLT_MAX;
        int   bg   = 0;
#pragma unroll
        for (int j = 0; j < 16; j++) {
            if (myv[j] > best) { best = myv[j]; bg = t + 256 * j; }
        }
#pragma unroll
        for (int off = 16; off > 0; off >>= 1) {
            float ov = __shfl_down_sync(0xffffffffu, best, off);
            int   og = __shfl_down_sync(0xffffffffu, bg, off);
            if (ov > best || (ov == best && og < bg)) { best = ov; bg = og; }
        }
        if (lid == 0) { s_rv[wid] = best; s_ri[wid] = bg; }
        __syncthreads();
        if (t == 0) {
            float bb = s_rv[0]; int bi = s_ri[0];
#pragma unroll
            for (int w2i = 1; w2i < NT / 32; w2i++) {
                if (s_rv[w2i] > bb || (s_rv[w2i] == bb && s_ri[w2i] < bi)) {
                    bb = s_rv[w2i]; bi = s_ri[w2i];
                }
            }
            s_w[sel] = bb; s_tau[sel] = bi;
        }
        __syncthreads();
        int win = s_tau[sel];
#pragma unroll
        for (int j = 0; j < 16; j++)
            if (win == t + 256 * j) myv[j] = -FLT_MAX;
    }

    // ===== time-delay aggregation: out[t'] = sum_k w_k * V[(t' + tau_k) & (N-1)]
    float wv[TOPK]; int dv[TOPK];
#pragma unroll
    for (int kk = 0; kk < TOPK; kk++) { wv[kk] = s_w[kk]; dv[kk] = s_tau[kk]; }
    float* outp = Ot + lane * FFT_N;
#pragma unroll 4
    for (int rr = 0; rr < 16; rr++) {
        int tp = t + 256 * rr;
        float acc = 0.0f;
#pragma unroll
        for (int kk = 0; kk < TOPK; kk++)
            acc += wv[kk] * Vs[(tp + dv[kk]) & (FFT_N - 1)];
        outp[tp] = acc;
    }
}

// -------- launch --------
extern "C" void kernel_launch(void* const* d_in, const int* in_sizes, int n_in,
                              void* d_out, int out_size) {
    (void)in_sizes; (void)n_in; (void)out_size;
    const float* Q = (const float*)d_in[0];
    const float* K = (const float*)d_in[1];
    const float* V = (const float*)d_in[2];
    float* out = (float*)d_out;

    float *Qt, *Kt, *Vt, *Ot;
    cudaGetSymbolAddress((void**)&Qt, g_Qt);
    cudaGetSymbolAddress((void**)&Kt, g_Kt);
    cudaGetSymbolAddress((void**)&Vt, g_Vt);
    cudaGetSymbolAddress((void**)&Ot, g_Ot);

    twiddle_init_kernel<<<(FFT_N + 255) / 256, 256>>>();

    dim3 tb(32, 8);
    transpose_in_kernel<<<dim3(ND / 32, FFT_N / 32, 3 * NB), tb>>>(Q, K, V);

    autocorr_fft4_kernel<<<NLANES, NT, FFT_N * sizeof(float2)>>>(Qt, Kt, Vt, Ot);

    transpose_out_kernel<<<dim3(FFT_N / 32, ND / 32, NB), tb>>>(out);
}